// round 2
// baseline (speedup 1.0000x reference)
#include <cuda_runtime.h>
#include <cuda_bf16.h>

#define B_    16
#define T_    2048
#define NTOK  (B_*T_)

// ---------------- scratch (static __device__, no allocations) ----------------
__device__ float g_x[NTOK*16];     // pre-attention residual x
__device__ float g_q[NTOK*6];      // q, head-interleaved pairs, pre-scaled by 1/sqrt(3)*log2(e)
__device__ float g_kv[NTOK*12];    // [kx01,ky01,kz01, vx01,vy01,vz01] head-interleaved
__device__ float g_attn[NTOK*6];   // attention output (h*3+d order)

typedef unsigned long long u64;

__device__ __forceinline__ u64 pack2(float lo, float hi){
    u64 r; asm("mov.b64 %0,{%1,%2};" : "=l"(r) : "f"(lo), "f"(hi)); return r;
}
__device__ __forceinline__ void unpack2(u64 v, float& lo, float& hi){
    asm("mov.b64 {%0,%1},%2;" : "=f"(lo), "=f"(hi) : "l"(v));
}
__device__ __forceinline__ u64 fma2(u64 a, u64 b, u64 c){
    u64 d; asm("fma.rn.f32x2 %0,%1,%2,%3;" : "=l"(d) : "l"(a), "l"(b), "l"(c)); return d;
}
__device__ __forceinline__ u64 mul2(u64 a, u64 b){
    u64 d; asm("mul.rn.f32x2 %0,%1,%2;" : "=l"(d) : "l"(a), "l"(b)); return d;
}
__device__ __forceinline__ u64 add2(u64 a, u64 b){
    u64 d; asm("add.rn.f32x2 %0,%1,%2;" : "=l"(d) : "l"(a), "l"(b)); return d;
}
__device__ __forceinline__ float ex2a(float x){
    float y; asm("ex2.approx.f32 %0,%1;" : "=f"(y) : "f"(x)); return y;
}

// ============================================================================
// K1: embed + LN1 + QKV projection (one thread per token)
// ============================================================================
__global__ void k1_qkv(const int* __restrict__ idx,
                       const float* __restrict__ tok_emb,
                       const float* __restrict__ pos_enc,
                       const float* __restrict__ Wq,
                       const float* __restrict__ Wk,
                       const float* __restrict__ Wv,
                       const float* __restrict__ ln1w,
                       const float* __restrict__ ln1b)
{
    int tok = blockIdx.x * 256 + threadIdx.x;
    if (tok >= NTOK) return;
    int t = tok & (T_ - 1);

    float x[16];
    int vtok = idx[tok];
    #pragma unroll
    for (int i = 0; i < 8; i++) x[i]     = __ldg(tok_emb + vtok*8 + i);
    #pragma unroll
    for (int i = 0; i < 8; i++) x[8 + i] = __ldg(pos_enc + t*8 + i);

    float m = 0.f;
    #pragma unroll
    for (int i = 0; i < 16; i++) m += x[i];
    m *= (1.f/16.f);
    float var = 0.f;
    #pragma unroll
    for (int i = 0; i < 16; i++){ float d = x[i] - m; var += d*d; }
    var *= (1.f/16.f);
    float rs = rsqrtf(var + 1e-5f);

    float h[16];
    #pragma unroll
    for (int i = 0; i < 16; i++)
        h[i] = (x[i] - m) * rs * __ldg(ln1w + i) + __ldg(ln1b + i);

    // store residual x
    float4* xs = reinterpret_cast<float4*>(g_x + (size_t)tok*16);
    xs[0] = make_float4(x[0],  x[1],  x[2],  x[3]);
    xs[1] = make_float4(x[4],  x[5],  x[6],  x[7]);
    xs[2] = make_float4(x[8],  x[9],  x[10], x[11]);
    xs[3] = make_float4(x[12], x[13], x[14], x[15]);

    // q,k from h[8..16) (pos part), v from h[0..8) (tok part)
    float q[6], k[6], vv[6];
    #pragma unroll
    for (int j = 0; j < 6; j++){
        float aq = 0.f, ak = 0.f, av = 0.f;
        #pragma unroll
        for (int d = 0; d < 8; d++){
            float hp = h[8 + d], ht = h[d];
            aq = fmaf(__ldg(Wq + j*8 + d), hp, aq);
            ak = fmaf(__ldg(Wk + j*8 + d), hp, ak);
            av = fmaf(__ldg(Wv + j*8 + d), ht, av);
        }
        q[j] = aq; k[j] = ak; vv[j] = av;
    }

    // fold 1/sqrt(3) * log2(e) into q so the inner loop uses a bare ex2
    const float QS = 0.5773502691896258f * 1.4426950408889634f;
    float* gq = g_q  + (size_t)tok*6;
    float* gk = g_kv + (size_t)tok*12;
    #pragma unroll
    for (int d = 0; d < 3; d++){
        gq[2*d + 0]     = q[d]   * QS;
        gq[2*d + 1]     = q[3+d] * QS;
        gk[2*d + 0]     = k[d];
        gk[2*d + 1]     = k[3+d];
        gk[6 + 2*d + 0] = vv[d];
        gk[6 + 2*d + 1] = vv[3+d];
    }
}

// ============================================================================
// K2: causal attention. One thread owns query pair (q, 2047-q) -> uniform work.
// Both heads packed into f32x2 lanes. No softmax-max (scores are tiny).
// ============================================================================
struct Acc { u64 ax, ay, az, den; };

__device__ __forceinline__ void upd(Acc& A, u64 qx, u64 qy, u64 qz,
                                    u64 kx, u64 ky, u64 kz,
                                    u64 vx, u64 vy, u64 vz)
{
    u64 s = fma2(qx, kx, fma2(qy, ky, mul2(qz, kz)));
    float s0, s1; unpack2(s, s0, s1);
    u64 e = pack2(ex2a(s0), ex2a(s1));
    A.den = add2(A.den, e);
    A.ax  = fma2(e, vx, A.ax);
    A.ay  = fma2(e, vy, A.ay);
    A.az  = fma2(e, vz, A.az);
}

__global__ void __launch_bounds__(128) k2_attn()
{
    int tid = blockIdx.x * 128 + threadIdx.x;   // 0 .. NTOK/2-1
    int b    = tid >> 10;                       // 1024 low-queries per batch
    int qlo  = tid & 1023;
    int qhi  = 2047 - qlo;
    int w0    = qlo & ~31;                      // warp-uniform (lanes consecutive)
    int whmin = 2016 - w0;                      // 2047 - (w0+31)
    int whmax = 2047 - w0;

    const u64* qpl = reinterpret_cast<const u64*>(g_q + ((size_t)b*T_ + qlo)*6);
    const u64* qph = reinterpret_cast<const u64*>(g_q + ((size_t)b*T_ + qhi)*6);
    u64 qlx = qpl[0], qly = qpl[1], qlz = qpl[2];
    u64 qhx = qph[0], qhy = qph[1], qhz = qph[2];

    Acc lo; lo.ax = lo.ay = lo.az = lo.den = 0ULL;
    Acc hi; hi.ax = hi.ay = hi.az = hi.den = 0ULL;

    const ulonglong2* kvp = reinterpret_cast<const ulonglong2*>(g_kv + (size_t)b*T_*12);

    int s = 0;
    // Phase A: s <= w0 : both queries, unconditional
    #pragma unroll 2
    for (; s <= w0; ++s){
        ulonglong2 p0 = kvp[3*s], p1 = kvp[3*s+1], p2 = kvp[3*s+2];
        upd(hi, qhx, qhy, qhz, p0.x, p0.y, p1.x, p1.y, p2.x, p2.y);
        upd(lo, qlx, qly, qlz, p0.x, p0.y, p1.x, p1.y, p2.x, p2.y);
    }
    // Phase B: ragged lo edge (31 iters): hi unconditional, lo predicated
    for (; s < w0 + 32; ++s){
        ulonglong2 p0 = kvp[3*s], p1 = kvp[3*s+1], p2 = kvp[3*s+2];
        upd(hi, qhx, qhy, qhz, p0.x, p0.y, p1.x, p1.y, p2.x, p2.y);
        if (s <= qlo)
            upd(lo, qlx, qly, qlz, p0.x, p0.y, p1.x, p1.y, p2.x, p2.y);
    }
    // Phase C: hi only, unconditional
    #pragma unroll 2
    for (; s <= whmin; ++s){
        ulonglong2 p0 = kvp[3*s], p1 = kvp[3*s+1], p2 = kvp[3*s+2];
        upd(hi, qhx, qhy, qhz, p0.x, p0.y, p1.x, p1.y, p2.x, p2.y);
    }
    // Phase D: ragged hi edge (31 iters)
    for (; s <= whmax; ++s){
        ulonglong2 p0 = kvp[3*s], p1 = kvp[3*s+1], p2 = kvp[3*s+2];
        if (s <= qhi)
            upd(hi, qhx, qhy, qhz, p0.x, p0.y, p1.x, p1.y, p2.x, p2.y);
    }

    // epilogue: normalize and write both queries
    {
        float ax0,ax1,ay0,ay1,az0,az1,d0,d1;
        unpack2(lo.ax,ax0,ax1); unpack2(lo.ay,ay0,ay1);
        unpack2(lo.az,az0,az1); unpack2(lo.den,d0,d1);
        float r0 = 1.f/d0, r1 = 1.f/d1;
        float* o = g_attn + ((size_t)b*T_ + qlo)*6;
        o[0]=ax0*r0; o[1]=ay0*r0; o[2]=az0*r0;
        o[3]=ax1*r1; o[4]=ay1*r1; o[5]=az1*r1;
    }
    {
        float ax0,ax1,ay0,ay1,az0,az1,d0,d1;
        unpack2(hi.ax,ax0,ax1); unpack2(hi.ay,ay0,ay1);
        unpack2(hi.az,az0,az1); unpack2(hi.den,d0,d1);
        float r0 = 1.f/d0, r1 = 1.f/d1;
        float* o = g_attn + ((size_t)b*T_ + qhi)*6;
        o[0]=ax0*r0; o[1]=ay0*r0; o[2]=az0*r0;
        o[3]=ax1*r1; o[4]=ay1*r1; o[5]=az1*r1;
    }
}

// ============================================================================
// K3: Wo projection + residual + LN2 + FFN(gelu exact) + residual + LNf +
//     fused head matrix (Wh.T @ tok_emb.T) -> logits. One thread per token.
// ============================================================================
__global__ void k3_post(const float* __restrict__ Wo,
                        const float* __restrict__ ln2w, const float* __restrict__ ln2b,
                        const float* __restrict__ lnfw, const float* __restrict__ lnfb,
                        const float* __restrict__ W1,   const float* __restrict__ b1,
                        const float* __restrict__ W2,   const float* __restrict__ b2,
                        const float* __restrict__ Wh,   const float* __restrict__ tok_emb,
                        float* __restrict__ out)
{
    __shared__ float M[224];          // M[v][i] = sum_d tok_emb[v,d] * Wh[d,i]
    int lt = threadIdx.x;
    if (lt < 224){
        int v = lt >> 4, i = lt & 15;
        float sm = 0.f;
        #pragma unroll
        for (int d = 0; d < 8; d++)
            sm = fmaf(__ldg(tok_emb + v*8 + d), __ldg(Wh + d*16 + i), sm);
        M[lt] = sm;
    }
    __syncthreads();

    int tok = blockIdx.x * 256 + lt;
    if (tok >= NTOK) return;

    float x[16];
    const float4* xs = reinterpret_cast<const float4*>(g_x + (size_t)tok*16);
    float4 a0 = xs[0], a1 = xs[1], a2 = xs[2], a3 = xs[3];
    x[0]=a0.x; x[1]=a0.y; x[2]=a0.z; x[3]=a0.w;
    x[4]=a1.x; x[5]=a1.y; x[6]=a1.z; x[7]=a1.w;
    x[8]=a2.x; x[9]=a2.y; x[10]=a2.z; x[11]=a2.w;
    x[12]=a3.x; x[13]=a3.y; x[14]=a3.z; x[15]=a3.w;

    float o[6];
    const float* op = g_attn + (size_t)tok*6;
    #pragma unroll
    for (int j = 0; j < 6; j++) o[j] = op[j];

    // x += out @ Wo^T
    #pragma unroll
    for (int i = 0; i < 16; i++){
        float sm = x[i];
        #pragma unroll
        for (int j = 0; j < 6; j++)
            sm = fmaf(__ldg(Wo + i*6 + j), o[j], sm);
        x[i] = sm;
    }

    // LN2
    float m = 0.f;
    #pragma unroll
    for (int i = 0; i < 16; i++) m += x[i];
    m *= (1.f/16.f);
    float var = 0.f;
    #pragma unroll
    for (int i = 0; i < 16; i++){ float d = x[i] - m; var += d*d; }
    var *= (1.f/16.f);
    float rs = rsqrtf(var + 1e-5f);
    float h2[16];
    #pragma unroll
    for (int i = 0; i < 16; i++)
        h2[i] = (x[i] - m) * rs * __ldg(ln2w + i) + __ldg(ln2b + i);

    // FFN: gelu exact (erf)
    float g[3];
    #pragma unroll
    for (int j = 0; j < 3; j++){
        float f = __ldg(b1 + j);
        #pragma unroll
        for (int i = 0; i < 16; i++)
            f = fmaf(__ldg(W1 + j*16 + i), h2[i], f);
        g[j] = 0.5f * f * (1.f + erff(f * 0.7071067811865476f));
    }
    #pragma unroll
    for (int i = 0; i < 16; i++){
        float sm = x[i] + __ldg(b2 + i);
        sm = fmaf(__ldg(W2 + i*3 + 0), g[0], sm);
        sm = fmaf(__ldg(W2 + i*3 + 1), g[1], sm);
        sm = fmaf(__ldg(W2 + i*3 + 2), g[2], sm);
        x[i] = sm;
    }

    // LNf
    m = 0.f;
    #pragma unroll
    for (int i = 0; i < 16; i++) m += x[i];
    m *= (1.f/16.f);
    var = 0.f;
    #pragma unroll
    for (int i = 0; i < 16; i++){ float d = x[i] - m; var += d*d; }
    var *= (1.f/16.f);
    rs = rsqrtf(var + 1e-5f);
    float y[16];
    #pragma unroll
    for (int i = 0; i < 16; i++)
        y[i] = (x[i] - m) * rs * __ldg(lnfw + i) + __ldg(lnfb + i);

    // logits = y @ M^T
    float* op2 = out + (size_t)tok*14;
    #pragma unroll
    for (int v = 0; v < 14; v++){
        float sm = 0.f;
        #pragma unroll
        for (int i = 0; i < 16; i++)
            sm = fmaf(y[i], M[v*16 + i], sm);
        op2[v] = sm;
    }
}

// ============================================================================
extern "C" void kernel_launch(void* const* d_in, const int* in_sizes, int n_in,
                              void* d_out, int out_size)
{
    const int*   idx  = (const int*)  d_in[0];
    const float* tokE = (const float*)d_in[1];
    const float* posE = (const float*)d_in[2];
    const float* Wq   = (const float*)d_in[3];
    const float* Wk   = (const float*)d_in[4];
    const float* Wv   = (const float*)d_in[5];
    const float* Wo   = (const float*)d_in[6];
    const float* ln1w = (const float*)d_in[7];
    const float* ln1b = (const float*)d_in[8];
    const float* ln2w = (const float*)d_in[9];
    const float* ln2b = (const float*)d_in[10];
    const float* lnfw = (const float*)d_in[11];
    const float* lnfb = (const float*)d_in[12];
    const float* W1   = (const float*)d_in[13];
    const float* b1   = (const float*)d_in[14];
    const float* W2   = (const float*)d_in[15];
    const float* b2   = (const float*)d_in[16];
    const float* Wh   = (const float*)d_in[17];
    float* out = (float*)d_out;

    k1_qkv<<<NTOK/256, 256>>>(idx, tokE, posE, Wq, Wk, Wv, ln1w, ln1b);
    k2_attn<<<(NTOK/2)/128, 128>>>();
    k3_post<<<NTOK/256, 256>>>(Wo, ln2w, ln2b, lnfw, lnfb, W1, b1, W2, b2, Wh, tokE, out);
}

// round 3
// speedup vs baseline: 4.8936x; 4.8936x over previous
#include <cuda_runtime.h>
#include <cuda_bf16.h>

#define B_    16
#define T_    2048
#define NTOK  (B_*T_)

// ---------------- scratch (static __device__, no allocations) ----------------
__device__ float g_x[NTOK*16];     // pre-attention residual x
__device__ float g_q[NTOK*6];      // q, head-interleaved pairs, pre-scaled by 1/sqrt(3)*log2(e)
__device__ float g_kv[NTOK*12];    // [kx01,ky01,kz01, vx01,vy01,vz01] head-interleaved
__device__ float g_attn[NTOK*6];   // attention output (h*3+d order), normalized

typedef unsigned long long u64;

__device__ __forceinline__ u64 pack2(float lo, float hi){
    u64 r; asm("mov.b64 %0,{%1,%2};" : "=l"(r) : "f"(lo), "f"(hi)); return r;
}
__device__ __forceinline__ void unpack2(u64 v, float& lo, float& hi){
    asm("mov.b64 {%0,%1},%2;" : "=f"(lo), "=f"(hi) : "l"(v));
}
__device__ __forceinline__ u64 fma2(u64 a, u64 b, u64 c){
    u64 d; asm("fma.rn.f32x2 %0,%1,%2,%3;" : "=l"(d) : "l"(a), "l"(b), "l"(c)); return d;
}
__device__ __forceinline__ u64 mul2(u64 a, u64 b){
    u64 d; asm("mul.rn.f32x2 %0,%1,%2;" : "=l"(d) : "l"(a), "l"(b)); return d;
}
__device__ __forceinline__ u64 add2(u64 a, u64 b){
    u64 d; asm("add.rn.f32x2 %0,%1,%2;" : "=l"(d) : "l"(a), "l"(b)); return d;
}
__device__ __forceinline__ float ex2a(float x){
    float y; asm("ex2.approx.f32 %0,%1;" : "=f"(y) : "f"(x)); return y;
}

// ============================================================================
// K1: embed + LN1 + QKV projection (one thread per token)
// ============================================================================
__global__ void k1_qkv(const int* __restrict__ idx,
                       const float* __restrict__ tok_emb,
                       const float* __restrict__ pos_enc,
                       const float* __restrict__ Wq,
                       const float* __restrict__ Wk,
                       const float* __restrict__ Wv,
                       const float* __restrict__ ln1w,
                       const float* __restrict__ ln1b)
{
    int tok = blockIdx.x * 256 + threadIdx.x;
    if (tok >= NTOK) return;
    int t = tok & (T_ - 1);

    float x[16];
    int vtok = idx[tok];
    #pragma unroll
    for (int i = 0; i < 8; i++) x[i]     = __ldg(tok_emb + vtok*8 + i);
    #pragma unroll
    for (int i = 0; i < 8; i++) x[8 + i] = __ldg(pos_enc + t*8 + i);

    float m = 0.f;
    #pragma unroll
    for (int i = 0; i < 16; i++) m += x[i];
    m *= (1.f/16.f);
    float var = 0.f;
    #pragma unroll
    for (int i = 0; i < 16; i++){ float d = x[i] - m; var += d*d; }
    var *= (1.f/16.f);
    float rs = rsqrtf(var + 1e-5f);

    float h[16];
    #pragma unroll
    for (int i = 0; i < 16; i++)
        h[i] = (x[i] - m) * rs * __ldg(ln1w + i) + __ldg(ln1b + i);

    // store residual x
    float4* xs = reinterpret_cast<float4*>(g_x + (size_t)tok*16);
    xs[0] = make_float4(x[0],  x[1],  x[2],  x[3]);
    xs[1] = make_float4(x[4],  x[5],  x[6],  x[7]);
    xs[2] = make_float4(x[8],  x[9],  x[10], x[11]);
    xs[3] = make_float4(x[12], x[13], x[14], x[15]);

    // q,k from h[8..16) (pos part), v from h[0..8) (tok part)
    float q[6], k[6], vv[6];
    #pragma unroll
    for (int j = 0; j < 6; j++){
        float aq = 0.f, ak = 0.f, av = 0.f;
        #pragma unroll
        for (int d = 0; d < 8; d++){
            float hp = h[8 + d], ht = h[d];
            aq = fmaf(__ldg(Wq + j*8 + d), hp, aq);
            ak = fmaf(__ldg(Wk + j*8 + d), hp, ak);
            av = fmaf(__ldg(Wv + j*8 + d), ht, av);
        }
        q[j] = aq; k[j] = ak; vv[j] = av;
    }

    // fold 1/sqrt(3) * log2(e) into q so the inner loop uses a bare ex2
    const float QS = 0.5773502691896258f * 1.4426950408889634f;
    float* gq = g_q  + (size_t)tok*6;
    float* gk = g_kv + (size_t)tok*12;
    #pragma unroll
    for (int d = 0; d < 3; d++){
        gq[2*d + 0]     = q[d]   * QS;
        gq[2*d + 1]     = q[3+d] * QS;
        gk[2*d + 0]     = k[d];
        gk[2*d + 1]     = k[3+d];
        gk[6 + 2*d + 0] = vv[d];
        gk[6 + 2*d + 1] = vv[3+d];
    }
}

// ============================================================================
// K2: causal attention, split-KV version.
// Block = 256 threads = 8 warps. Warp w = sequence split (positions w, w+8, ...),
// lane l = query pair (qlo = base+l, qhi = 2047-qlo). KV loads stay warp-uniform
// (broadcast, 1 wavefront). Partial softmax sums are additive (no max needed),
// reduced across the 8 warps in shared memory, normalized, written once.
// ============================================================================
struct Acc { u64 ax, ay, az, den; };

__device__ __forceinline__ void upd(Acc& A, u64 qx, u64 qy, u64 qz,
                                    u64 kx, u64 ky, u64 kz,
                                    u64 vx, u64 vy, u64 vz)
{
    u64 s = fma2(qx, kx, fma2(qy, ky, mul2(qz, kz)));
    float s0, s1; unpack2(s, s0, s1);
    u64 e = pack2(ex2a(s0), ex2a(s1));
    A.den = add2(A.den, e);
    A.ax  = fma2(e, vx, A.ax);
    A.ay  = fma2(e, vy, A.ay);
    A.az  = fma2(e, vz, A.az);
}

__global__ void __launch_bounds__(256) k2_attn()
{
    __shared__ float red[8][32][17];            // padded: conflict-free

    int w    = threadIdx.x >> 5;                // split index 0..7
    int l    = threadIdx.x & 31;                // pair index within group
    int b    = blockIdx.x >> 5;                 // batch
    int base = (blockIdx.x & 31) << 5;          // qlo group base (0,32,...,992)
    int qlo  = base + l;
    int qhi  = 2047 - qlo;

    const u64* qpl = reinterpret_cast<const u64*>(g_q + ((size_t)b*T_ + qlo)*6);
    const u64* qph = reinterpret_cast<const u64*>(g_q + ((size_t)b*T_ + qhi)*6);
    u64 qlx = qpl[0], qly = qpl[1], qlz = qpl[2];
    u64 qhx = qph[0], qhy = qph[1], qhz = qph[2];

    Acc lo; lo.ax = lo.ay = lo.az = lo.den = 0ULL;
    Acc hi; hi.ax = hi.ay = hi.az = hi.den = 0ULL;

    const ulonglong2* kvp = reinterpret_cast<const ulonglong2*>(g_kv + (size_t)b*T_*12);

    int p = w;
    // Phase A: p <= base : both queries, unconditional
    #pragma unroll 2
    for (; p <= base; p += 8){
        ulonglong2 p0 = kvp[3*p], p1 = kvp[3*p+1], p2 = kvp[3*p+2];
        upd(hi, qhx, qhy, qhz, p0.x, p0.y, p1.x, p1.y, p2.x, p2.y);
        upd(lo, qlx, qly, qlz, p0.x, p0.y, p1.x, p1.y, p2.x, p2.y);
    }
    // Phase B: ragged lo edge: hi unconditional, lo predicated
    for (; p < base + 32; p += 8){
        ulonglong2 p0 = kvp[3*p], p1 = kvp[3*p+1], p2 = kvp[3*p+2];
        upd(hi, qhx, qhy, qhz, p0.x, p0.y, p1.x, p1.y, p2.x, p2.y);
        if (p <= qlo)
            upd(lo, qlx, qly, qlz, p0.x, p0.y, p1.x, p1.y, p2.x, p2.y);
    }
    // Phase C: hi only, unconditional (p <= qhi_min = 2016 - base)
    int cmax = 2016 - base;
    #pragma unroll 4
    for (; p <= cmax; p += 8){
        ulonglong2 p0 = kvp[3*p], p1 = kvp[3*p+1], p2 = kvp[3*p+2];
        upd(hi, qhx, qhy, qhz, p0.x, p0.y, p1.x, p1.y, p2.x, p2.y);
    }
    // Phase D: ragged hi edge
    int dmax = 2047 - base;
    for (; p <= dmax; p += 8){
        ulonglong2 p0 = kvp[3*p], p1 = kvp[3*p+1], p2 = kvp[3*p+2];
        if (p <= qhi)
            upd(hi, qhx, qhy, qhz, p0.x, p0.y, p1.x, p1.y, p2.x, p2.y);
    }

    // ---- cross-warp reduction in smem ----
    {
        float t0, t1;
        unpack2(lo.den, t0, t1); red[w][l][0]  = t0; red[w][l][4]  = t1;
        unpack2(lo.ax,  t0, t1); red[w][l][1]  = t0; red[w][l][5]  = t1;
        unpack2(lo.ay,  t0, t1); red[w][l][2]  = t0; red[w][l][6]  = t1;
        unpack2(lo.az,  t0, t1); red[w][l][3]  = t0; red[w][l][7]  = t1;
        unpack2(hi.den, t0, t1); red[w][l][8]  = t0; red[w][l][12] = t1;
        unpack2(hi.ax,  t0, t1); red[w][l][9]  = t0; red[w][l][13] = t1;
        unpack2(hi.ay,  t0, t1); red[w][l][10] = t0; red[w][l][14] = t1;
        unpack2(hi.az,  t0, t1); red[w][l][11] = t0; red[w][l][15] = t1;
    }
    __syncthreads();

    if (threadIdx.x < 64){
        int l2 = threadIdx.x & 31;
        int hh = threadIdx.x >> 5;              // 0 = lo query, 1 = hi query
        float a[8];
        #pragma unroll
        for (int j = 0; j < 8; j++) a[j] = 0.f;
        #pragma unroll
        for (int ww = 0; ww < 8; ww++){
            #pragma unroll
            for (int j = 0; j < 8; j++)
                a[j] += red[ww][l2][hh*8 + j];
        }
        int q = hh ? (2047 - (base + l2)) : (base + l2);
        float r0 = 1.f / a[0];
        float r1 = 1.f / a[4];
        float* o = g_attn + ((size_t)b*T_ + q)*6;
        o[0] = a[1]*r0; o[1] = a[2]*r0; o[2] = a[3]*r0;
        o[3] = a[5]*r1; o[4] = a[6]*r1; o[5] = a[7]*r1;
    }
}

// ============================================================================
// K3: Wo projection + residual + LN2 + FFN(gelu exact) + residual + LNf +
//     fused head matrix (Wh.T @ tok_emb.T) -> logits. One thread per token.
// ============================================================================
__global__ void k3_post(const float* __restrict__ Wo,
                        const float* __restrict__ ln2w, const float* __restrict__ ln2b,
                        const float* __restrict__ lnfw, const float* __restrict__ lnfb,
                        const float* __restrict__ W1,   const float* __restrict__ b1,
                        const float* __restrict__ W2,   const float* __restrict__ b2,
                        const float* __restrict__ Wh,   const float* __restrict__ tok_emb,
                        float* __restrict__ out)
{
    __shared__ float M[224];          // M[v][i] = sum_d tok_emb[v,d] * Wh[d,i]
    int lt = threadIdx.x;
    if (lt < 224){
        int v = lt >> 4, i = lt & 15;
        float sm = 0.f;
        #pragma unroll
        for (int d = 0; d < 8; d++)
            sm = fmaf(__ldg(tok_emb + v*8 + d), __ldg(Wh + d*16 + i), sm);
        M[lt] = sm;
    }
    __syncthreads();

    int tok = blockIdx.x * 256 + lt;
    if (tok >= NTOK) return;

    float x[16];
    const float4* xs = reinterpret_cast<const float4*>(g_x + (size_t)tok*16);
    float4 a0 = xs[0], a1 = xs[1], a2 = xs[2], a3 = xs[3];
    x[0]=a0.x; x[1]=a0.y; x[2]=a0.z; x[3]=a0.w;
    x[4]=a1.x; x[5]=a1.y; x[6]=a1.z; x[7]=a1.w;
    x[8]=a2.x; x[9]=a2.y; x[10]=a2.z; x[11]=a2.w;
    x[12]=a3.x; x[13]=a3.y; x[14]=a3.z; x[15]=a3.w;

    float o[6];
    const float* op = g_attn + (size_t)tok*6;
    #pragma unroll
    for (int j = 0; j < 6; j++) o[j] = op[j];

    // x += out @ Wo^T
    #pragma unroll
    for (int i = 0; i < 16; i++){
        float sm = x[i];
        #pragma unroll
        for (int j = 0; j < 6; j++)
            sm = fmaf(__ldg(Wo + i*6 + j), o[j], sm);
        x[i] = sm;
    }

    // LN2
    float m = 0.f;
    #pragma unroll
    for (int i = 0; i < 16; i++) m += x[i];
    m *= (1.f/16.f);
    float var = 0.f;
    #pragma unroll
    for (int i = 0; i < 16; i++){ float d = x[i] - m; var += d*d; }
    var *= (1.f/16.f);
    float rs = rsqrtf(var + 1e-5f);
    float h2[16];
    #pragma unroll
    for (int i = 0; i < 16; i++)
        h2[i] = (x[i] - m) * rs * __ldg(ln2w + i) + __ldg(ln2b + i);

    // FFN: gelu exact (erf)
    float g[3];
    #pragma unroll
    for (int j = 0; j < 3; j++){
        float f = __ldg(b1 + j);
        #pragma unroll
        for (int i = 0; i < 16; i++)
            f = fmaf(__ldg(W1 + j*16 + i), h2[i], f);
        g[j] = 0.5f * f * (1.f + erff(f * 0.7071067811865476f));
    }
    #pragma unroll
    for (int i = 0; i < 16; i++){
        float sm = x[i] + __ldg(b2 + i);
        sm = fmaf(__ldg(W2 + i*3 + 0), g[0], sm);
        sm = fmaf(__ldg(W2 + i*3 + 1), g[1], sm);
        sm = fmaf(__ldg(W2 + i*3 + 2), g[2], sm);
        x[i] = sm;
    }

    // LNf
    m = 0.f;
    #pragma unroll
    for (int i = 0; i < 16; i++) m += x[i];
    m *= (1.f/16.f);
    var = 0.f;
    #pragma unroll
    for (int i = 0; i < 16; i++){ float d = x[i] - m; var += d*d; }
    var *= (1.f/16.f);
    rs = rsqrtf(var + 1e-5f);
    float y[16];
    #pragma unroll
    for (int i = 0; i < 16; i++)
        y[i] = (x[i] - m) * rs * __ldg(lnfw + i) + __ldg(lnfb + i);

    // logits = y @ M^T
    float* op2 = out + (size_t)tok*14;
    #pragma unroll
    for (int v = 0; v < 14; v++){
        float sm = 0.f;
        #pragma unroll
        for (int i = 0; i < 16; i++)
            sm = fmaf(y[i], M[v*16 + i], sm);
        op2[v] = sm;
    }
}

// ============================================================================
extern "C" void kernel_launch(void* const* d_in, const int* in_sizes, int n_in,
                              void* d_out, int out_size)
{
    const int*   idx  = (const int*)  d_in[0];
    const float* tokE = (const float*)d_in[1];
    const float* posE = (const float*)d_in[2];
    const float* Wq   = (const float*)d_in[3];
    const float* Wk   = (const float*)d_in[4];
    const float* Wv   = (const float*)d_in[5];
    const float* Wo   = (const float*)d_in[6];
    const float* ln1w = (const float*)d_in[7];
    const float* ln1b = (const float*)d_in[8];
    const float* ln2w = (const float*)d_in[9];
    const float* ln2b = (const float*)d_in[10];
    const float* lnfw = (const float*)d_in[11];
    const float* lnfb = (const float*)d_in[12];
    const float* W1   = (const float*)d_in[13];
    const float* b1   = (const float*)d_in[14];
    const float* W2   = (const float*)d_in[15];
    const float* b2   = (const float*)d_in[16];
    const float* Wh   = (const float*)d_in[17];
    float* out = (float*)d_out;

    k1_qkv<<<NTOK/256, 256>>>(idx, tokE, posE, Wq, Wk, Wv, ln1w, ln1b);
    k2_attn<<<16*32, 256>>>();
    k3_post<<<NTOK/256, 256>>>(Wo, ln2w, ln2b, lnfw, lnfb, W1, b1, W2, b2, Wh, tokE, out);
}